// round 14
// baseline (speedup 1.0000x reference)
#include <cuda_runtime.h>
#include <cuda_bf16.h>
#include <cstdint>
#include <math.h>

// kv (16,1024,259) f32, positions (16,1024,3) f32, out (16,1024,3) f32
#define BATCH     16
#define NN        1024
#define EE        128
#define CC        259
#define TN        64           // n rows per block (2 blocks/SM)
#define TM        64           // m cols per tile
#define NT        (NN / TM)    // 16 tiles
#define NTH       512          // 16 warps: 4 n-groups x 4 m-col quarters
#define INV_SQRT_E 0.0883883476483184406f

// smem rows: 128 bf16 + 8 pad = 272 B (17 x 16B -> ldmatrix conflict-free)
#define ROWB      272
#define OFF_PM    0                           // pm ring: 2 x 64*3 floats
#define PM_BYTES  (2 * TM * 3 * 4)            // 1536
#define OFF_KHI   PM_BYTES                    // 1536
#define KMAT      (TN * ROWB)                 // 17408
#define OFF_KLO   (OFF_KHI + KMAT)            // 18944
#define OFF_V     (OFF_KLO + KMAT)            // 36352
#define VMAT      (TM * ROWB)                 // 17408
#define VBUF      (2 * VMAT)                  // vhi + vlo = 34816
#define SMEM_TOTAL (OFF_V + 2 * VBUF)         // 105984 B  (2 blocks/SM: 211968 <= 228KB)

// ---------------- PTX helpers ----------------
__device__ __forceinline__ uint32_t smem_u32(const void* p) {
    uint32_t a;
    asm("{ .reg .u64 t; cvta.to.shared.u64 t, %1; cvt.u32.u64 %0, t; }" : "=r"(a) : "l"(p));
    return a;
}
__device__ __forceinline__ void ldsm4(uint32_t* r, uint32_t addr) {
    asm volatile("ldmatrix.sync.aligned.m8n8.x4.shared.b16 {%0,%1,%2,%3}, [%4];"
                 : "=r"(r[0]), "=r"(r[1]), "=r"(r[2]), "=r"(r[3]) : "r"(addr));
}
__device__ __forceinline__ void mma_bf16(float* d, const uint32_t* a, uint32_t b0, uint32_t b1) {
    asm volatile(
        "mma.sync.aligned.m16n8k16.row.col.f32.bf16.bf16.f32 "
        "{%0,%1,%2,%3}, {%4,%5,%6,%7}, {%8,%9}, {%0,%1,%2,%3};"
        : "+f"(d[0]), "+f"(d[1]), "+f"(d[2]), "+f"(d[3])
        : "r"(a[0]), "r"(a[1]), "r"(a[2]), "r"(a[3]), "r"(b0), "r"(b1));
}
// split x into bf16 hi + bf16 lo (lo = bf16(x - float(hi)))
__device__ __forceinline__ void split2(float x0, float x1, uint32_t& hi, uint32_t& lo) {
    __nv_bfloat16 h0 = __float2bfloat16(x0), h1 = __float2bfloat16(x1);
    __nv_bfloat16 l0 = __float2bfloat16(x0 - __bfloat162float(h0));
    __nv_bfloat16 l1 = __float2bfloat16(x1 - __bfloat162float(h1));
    hi = (uint32_t)__bfloat16_as_ushort(h0) | ((uint32_t)__bfloat16_as_ushort(h1) << 16);
    lo = (uint32_t)__bfloat16_as_ushort(l0) | ((uint32_t)__bfloat16_as_ushort(l1) << 16);
}

__global__ __launch_bounds__(NTH, 2)
void actor_mma_kernel(const float* __restrict__ kv,
                      const float* __restrict__ pos,
                      float* __restrict__ out)
{
    extern __shared__ char smem[];
    const uint32_t sb = smem_u32(smem);
    float* pm_s = (float*)(smem + OFF_PM);    // [2][TM*3]

    const int tid  = threadIdx.x;
    const int w    = tid >> 5;
    const int lane = tid & 31;
    const int wn   = w & 3;            // n-row group: rows wn*16 .. wn*16+15
    const int wm   = w >> 2;           // m-col quarter: cols wm*16 .. wm*16+15
    const int b    = blockIdx.y;
    const int n0   = blockIdx.x * TN;

    const float* kvb  = kv  + (size_t)b * NN * CC;
    const float* posb = pos + (size_t)b * NN * 3;

    // ---- stage K (prescaled), split hi/lo: 64 rows x 32 float4-groups ----
    for (int q = tid; q < TN * 32; q += NTH) {
        int r = q >> 5, c4 = q & 31;
        const float* src = kvb + (size_t)(n0 + r) * CC + c4 * 4;
        float x0 = src[0] * INV_SQRT_E, x1 = src[1] * INV_SQRT_E;
        float x2 = src[2] * INV_SQRT_E, x3 = src[3] * INV_SQRT_E;
        uint32_t h01, l01, h23, l23;
        split2(x0, x1, h01, l01);
        split2(x2, x3, h23, l23);
        uint32_t off = (uint32_t)r * ROWB + (uint32_t)c4 * 8;
        *(uint2*)(smem + OFF_KHI + off) = make_uint2(h01, h23);
        *(uint2*)(smem + OFF_KLO + off) = make_uint2(l01, l23);
    }
    // ---- stage V tile 0 + pm tile 0 ----
    for (int q = tid; q < TM * 32; q += NTH) {
        int r = q >> 5, c4 = q & 31;
        const float* src = kvb + (size_t)r * CC + EE + c4 * 4;
        uint32_t h01, l01, h23, l23;
        split2(src[0], src[1], h01, l01);
        split2(src[2], src[3], h23, l23);
        uint32_t off = (uint32_t)r * ROWB + (uint32_t)c4 * 8;
        *(uint2*)(smem + OFF_V + off)        = make_uint2(h01, h23);
        *(uint2*)(smem + OFF_V + VMAT + off) = make_uint2(l01, l23);
    }
    if (tid < TM * 3) pm_s[tid] = posb[tid];
    __syncthreads();

    // ---- per-thread n-row state (2 rows) ----
    const int r0loc = wn * 16 + (lane >> 2);      // local n row; second = +8
    const float pn0x = posb[(size_t)(n0 + r0loc) * 3 + 0];
    const float pn0y = posb[(size_t)(n0 + r0loc) * 3 + 1];
    const float pn0z = posb[(size_t)(n0 + r0loc) * 3 + 2];
    const float pn1x = posb[(size_t)(n0 + r0loc + 8) * 3 + 0];
    const float pn1y = posb[(size_t)(n0 + r0loc + 8) * 3 + 1];
    const float pn1z = posb[(size_t)(n0 + r0loc + 8) * 3 + 2];
    float a0x = 0.f, a0y = 0.f, a0z = 0.f, a1x = 0.f, a1y = 0.f, a1z = 0.f;

    // ldmatrix lane address components
    const uint32_t a_row  = (uint32_t)(wn * 16 + (lane & 15));
    const uint32_t a_coff = (uint32_t)(lane >> 4) * 16;
    const uint32_t b_row  = (uint32_t)(wm * 16 + (lane & 7) + ((lane >> 4) & 1) * 8);
    const uint32_t b_coff = (uint32_t)((lane >> 3) & 1) * 16;
    const uint32_t a_hi_base = sb + OFF_KHI + a_row * ROWB + a_coff;
    const uint32_t a_lo_base = sb + OFF_KLO + a_row * ROWB + a_coff;

    #pragma unroll 1
    for (int t = 0; t < NT; t++) {
        // ---- stage V(t+1)/pm(t+1) BEFORE MMA: keeps vreg live range short ----
        if (t + 1 < NT) {
            const float* vsrc = kvb + (size_t)(t + 1) * TM * CC + EE;
            char* dst = smem + OFF_V + ((t + 1) & 1) * VBUF;
            float vreg[16];
            #pragma unroll
            for (int i = 0; i < 4; i++) {
                int q = i * NTH + tid;
                int r = q >> 5, c4 = q & 31;
                const float* s = vsrc + (size_t)r * CC + c4 * 4;
                vreg[i*4+0] = s[0]; vreg[i*4+1] = s[1];
                vreg[i*4+2] = s[2]; vreg[i*4+3] = s[3];
            }
            #pragma unroll
            for (int i = 0; i < 4; i++) {
                int q = i * NTH + tid;
                int r = q >> 5, c4 = q & 31;
                uint32_t h01, l01, h23, l23;
                split2(vreg[i*4+0], vreg[i*4+1], h01, l01);
                split2(vreg[i*4+2], vreg[i*4+3], h23, l23);
                uint32_t off = (uint32_t)r * ROWB + (uint32_t)c4 * 8;
                *(uint2*)(dst + off)        = make_uint2(h01, h23);
                *(uint2*)(dst + VMAT + off) = make_uint2(l01, l23);
            }
            if (tid < TM * 3)
                pm_s[((t + 1) & 1) * TM * 3 + tid] = posb[(size_t)(t + 1) * TM * 3 + tid];
        }

        // ---- MMA: this warp's 16 m-cols of tile t ----
        const uint32_t vb    = sb + OFF_V + (uint32_t)(t & 1) * VBUF;
        const uint32_t b_hi0 = vb + b_row * ROWB + b_coff;
        const uint32_t b_lo0 = b_hi0 + VMAT;

        float acc[2][4];
        #pragma unroll
        for (int i = 0; i < 2; i++)
            #pragma unroll
            for (int j = 0; j < 4; j++) acc[i][j] = 0.f;

        #pragma unroll
        for (int k = 0; k < 8; k++) {
            uint32_t ahi[4], alo[4], bhi[4], blo[4];
            ldsm4(ahi, a_hi_base + (uint32_t)k * 32);
            ldsm4(alo, a_lo_base + (uint32_t)k * 32);
            ldsm4(bhi, b_hi0 + (uint32_t)k * 32);
            ldsm4(blo, b_lo0 + (uint32_t)k * 32);
            mma_bf16(acc[0], ahi, bhi[0], bhi[1]);   // hi*hi
            mma_bf16(acc[1], ahi, bhi[2], bhi[3]);
            mma_bf16(acc[0], ahi, blo[0], blo[1]);   // hi*lo
            mma_bf16(acc[1], ahi, blo[2], blo[3]);
            mma_bf16(acc[0], alo, bhi[0], bhi[1]);   // lo*hi
            mma_bf16(acc[1], alo, bhi[2], bhi[3]);
        }

        // ---- fused epilogue on this warp's 16 m-cols ----
        const float* pm_t = pm_s + (t & 1) * TM * 3;
        #pragma unroll
        for (int bi = 0; bi < 2; bi++) {
            #pragma unroll
            for (int cc = 0; cc < 2; cc++) {
                int ml = wm * 16 + bi * 8 + (lane & 3) * 2 + cc;
                const float* pm = pm_t + ml * 3;
                float pmx = pm[0], pmy = pm[1], pmz = pm[2];
                {
                    float dx = pn0x - pmx, dy = pn0y - pmy, dz = pn0z - pmz;
                    float sq = fmaf(dx, dx, fmaf(dy, dy, fmaf(dz, dz, 1e-30f)));
                    float wg = acc[bi][cc] * rsqrtf(sq);     // diagonal: 0*finite=0
                    a0x = fmaf(dx, wg, a0x); a0y = fmaf(dy, wg, a0y); a0z = fmaf(dz, wg, a0z);
                }
                {
                    float dx = pn1x - pmx, dy = pn1y - pmy, dz = pn1z - pmz;
                    float sq = fmaf(dx, dx, fmaf(dy, dy, fmaf(dz, dz, 1e-30f)));
                    float wg = acc[bi][2 + cc] * rsqrtf(sq);
                    a1x = fmaf(dx, wg, a1x); a1y = fmaf(dy, wg, a1y); a1z = fmaf(dz, wg, a1z);
                }
            }
        }
        __syncthreads();
    }

    // ---- reduce across the 4 lanes of each quad (same rows, different m-cols) ----
    #pragma unroll
    for (int off = 1; off <= 2; off <<= 1) {
        a0x += __shfl_xor_sync(0xffffffffu, a0x, off);
        a0y += __shfl_xor_sync(0xffffffffu, a0y, off);
        a0z += __shfl_xor_sync(0xffffffffu, a0z, off);
        a1x += __shfl_xor_sync(0xffffffffu, a1x, off);
        a1y += __shfl_xor_sync(0xffffffffu, a1y, off);
        a1z += __shfl_xor_sync(0xffffffffu, a1z, off);
    }

    // ---- combine the 4 m-col quarters via smem scratch (V region dead) ----
    float* scr = (float*)(smem + OFF_V);      // [4][TN*3]
    if ((lane & 3) == 0) {
        float* s0 = scr + wm * TN * 3;
        s0[r0loc * 3 + 0] = a0x;  s0[r0loc * 3 + 1] = a0y;  s0[r0loc * 3 + 2] = a0z;
        s0[(r0loc + 8) * 3 + 0] = a1x;
        s0[(r0loc + 8) * 3 + 1] = a1y;
        s0[(r0loc + 8) * 3 + 2] = a1z;
    }
    __syncthreads();
    if (wm == 0 && (lane & 3) == 0) {
        #pragma unroll
        for (int rr = 0; rr < 2; rr++) {
            int rl = r0loc + rr * 8;
            float ax = 0.f, ay = 0.f, az = 0.f;
            #pragma unroll
            for (int g = 0; g < 4; g++) {
                const float* s0 = scr + g * TN * 3 + rl * 3;
                ax += s0[0]; ay += s0[1]; az += s0[2];
            }
            float* o = out + ((size_t)b * NN + n0 + rl) * 3;
            o[0] = 0.01f * tanhf(ax);
            o[1] = 0.01f * tanhf(ay);
            o[2] = 0.01f * tanhf(az);
        }
    }
}

extern "C" void kernel_launch(void* const* d_in, const int* in_sizes, int n_in,
                              void* d_out, int out_size)
{
    const float* kv  = (const float*)d_in[0];
    const float* pos = (const float*)d_in[1];
    float* out = (float*)d_out;
    (void)in_sizes; (void)n_in; (void)out_size;

    cudaFuncSetAttribute(actor_mma_kernel,
                         cudaFuncAttributeMaxDynamicSharedMemorySize, SMEM_TOTAL);

    dim3 grid(NN / TN, BATCH);   // (16,16) = 256 blocks, 2 per SM, single wave
    actor_mma_kernel<<<grid, NTH, SMEM_TOTAL>>>(kv, pos, out);
}

// round 15
// speedup vs baseline: 1.3377x; 1.3377x over previous
#include <cuda_runtime.h>
#include <cuda_bf16.h>
#include <cstdint>
#include <math.h>

// kv (16,1024,259) f32, positions (16,1024,3) f32, out (16,1024,3) f32
#define BATCH     16
#define NN        1024
#define EE        128
#define CC        259
#define TN        128          // n rows per block
#define TM        64           // m cols per tile
#define NT        (NN / TM)    // 16 tiles
#define NTH       512          // 16 warps: 8 n-groups x 2 m-col halves
#define INV_SQRT_E 0.0883883476483184406f

// smem rows: 128 bf16 + 8 pad = 272 B (17 x 16B -> ldmatrix conflict-free)
#define ROWB      272
#define OFF_POS   0
#define POS_BYTES (NN * 3 * 4)               // 12288
#define OFF_KHI   (OFF_POS + POS_BYTES)      // 12288
#define KMAT      (TN * ROWB)                // 34816
#define OFF_KLO   (OFF_KHI + KMAT)           // 47104
#define OFF_V     (OFF_KLO + KMAT)           // 81920
#define VMAT      (TM * ROWB)                // 17408
#define VBUF      (2 * VMAT)                 // vhi + vlo = 34816
#define SMEM_TOTAL (OFF_V + 4 * VBUF)        // 221184 B (quad-buffered V)

// ---------------- PTX helpers ----------------
__device__ __forceinline__ uint32_t smem_u32(const void* p) {
    uint32_t a;
    asm("{ .reg .u64 t; cvta.to.shared.u64 t, %1; cvt.u32.u64 %0, t; }" : "=r"(a) : "l"(p));
    return a;
}
__device__ __forceinline__ void ldsm4(uint32_t* r, uint32_t addr) {
    asm volatile("ldmatrix.sync.aligned.m8n8.x4.shared.b16 {%0,%1,%2,%3}, [%4];"
                 : "=r"(r[0]), "=r"(r[1]), "=r"(r[2]), "=r"(r[3]) : "r"(addr));
}
__device__ __forceinline__ void mma_bf16(float* d, const uint32_t* a, uint32_t b0, uint32_t b1) {
    asm volatile(
        "mma.sync.aligned.m16n8k16.row.col.f32.bf16.bf16.f32 "
        "{%0,%1,%2,%3}, {%4,%5,%6,%7}, {%8,%9}, {%0,%1,%2,%3};"
        : "+f"(d[0]), "+f"(d[1]), "+f"(d[2]), "+f"(d[3])
        : "r"(a[0]), "r"(a[1]), "r"(a[2]), "r"(a[3]), "r"(b0), "r"(b1));
}
// split x into bf16 hi + bf16 lo (lo = bf16(x - float(hi)))
__device__ __forceinline__ void split2(float x0, float x1, uint32_t& hi, uint32_t& lo) {
    __nv_bfloat16 h0 = __float2bfloat16(x0), h1 = __float2bfloat16(x1);
    __nv_bfloat16 l0 = __float2bfloat16(x0 - __bfloat162float(h0));
    __nv_bfloat16 l1 = __float2bfloat16(x1 - __bfloat162float(h1));
    hi = (uint32_t)__bfloat16_as_ushort(h0) | ((uint32_t)__bfloat16_as_ushort(h1) << 16);
    lo = (uint32_t)__bfloat16_as_ushort(l0) | ((uint32_t)__bfloat16_as_ushort(l1) << 16);
}

__global__ __launch_bounds__(NTH, 1)
void actor_mma_kernel(const float* __restrict__ kv,
                      const float* __restrict__ pos,
                      float* __restrict__ out)
{
    extern __shared__ char smem[];
    const uint32_t sb = smem_u32(smem);
    float* pos_s = (float*)(smem + OFF_POS);

    const int tid  = threadIdx.x;
    const int w    = tid >> 5;
    const int lane = tid & 31;
    const int wn   = w & 7;            // n-row group: rows wn*16 .. wn*16+15
    const int wm   = w >> 3;           // m-col half: cols wm*32 .. wm*32+31 of each tile
    const int b    = blockIdx.y;
    const int n0   = blockIdx.x * TN;

    const float* kvb  = kv  + (size_t)b * NN * CC;
    const float* posb = pos + (size_t)b * NN * 3;

    // ---- stage all m positions ----
    for (int i = tid; i < NN * 3; i += NTH) pos_s[i] = posb[i];

    // ---- stage K (prescaled), split hi/lo ----
    for (int q = tid; q < TN * 32; q += NTH) {           // 32 float4-groups/row
        int r = q >> 5, c4 = q & 31;
        const float* src = kvb + (size_t)(n0 + r) * CC + c4 * 4;
        float x0 = src[0] * INV_SQRT_E, x1 = src[1] * INV_SQRT_E;
        float x2 = src[2] * INV_SQRT_E, x3 = src[3] * INV_SQRT_E;
        uint32_t h01, l01, h23, l23;
        split2(x0, x1, h01, l01);
        split2(x2, x3, h23, l23);
        uint32_t off = (uint32_t)r * ROWB + (uint32_t)c4 * 8;
        *(uint2*)(smem + OFF_KHI + off) = make_uint2(h01, h23);
        *(uint2*)(smem + OFF_KLO + off) = make_uint2(l01, l23);
    }

    // ---- stage V tiles 0 and 1 (prologue fills two buffers) ----
    for (int t0 = 0; t0 < 2; t0++) {
        char* dst = smem + OFF_V + t0 * VBUF;
        const float* vsrc = kvb + (size_t)t0 * TM * CC + EE;
        for (int q = tid; q < TM * 32; q += NTH) {
            int r = q >> 5, c4 = q & 31;
            const float* src = vsrc + (size_t)r * CC + c4 * 4;
            uint32_t h01, l01, h23, l23;
            split2(src[0], src[1], h01, l01);
            split2(src[2], src[3], h23, l23);
            uint32_t off = (uint32_t)r * ROWB + (uint32_t)c4 * 8;
            *(uint2*)(dst + off)        = make_uint2(h01, h23);
            *(uint2*)(dst + VMAT + off) = make_uint2(l01, l23);
        }
    }
    __syncthreads();

    // ---- per-thread n-row state (2 rows) ----
    const int r0loc = wn * 16 + (lane >> 2);      // local n row; second = +8
    const float pn0x = posb[(size_t)(n0 + r0loc) * 3 + 0];
    const float pn0y = posb[(size_t)(n0 + r0loc) * 3 + 1];
    const float pn0z = posb[(size_t)(n0 + r0loc) * 3 + 2];
    const float pn1x = posb[(size_t)(n0 + r0loc + 8) * 3 + 0];
    const float pn1y = posb[(size_t)(n0 + r0loc + 8) * 3 + 1];
    const float pn1z = posb[(size_t)(n0 + r0loc + 8) * 3 + 2];
    float a0x = 0.f, a0y = 0.f, a0z = 0.f, a1x = 0.f, a1y = 0.f, a1z = 0.f;

    // ldmatrix lane address components
    const uint32_t a_row  = (uint32_t)(wn * 16 + (lane & 15));
    const uint32_t a_coff = (uint32_t)(lane >> 4) * 16;
    const uint32_t b_row  = (uint32_t)((lane & 7) + ((lane >> 4) & 1) * 8);
    const uint32_t b_coff = (uint32_t)((lane >> 3) & 1) * 16;
    const uint32_t a_hi_base = sb + OFF_KHI + a_row * ROWB + a_coff;
    const uint32_t a_lo_base = sb + OFF_KLO + a_row * ROWB + a_coff;

    float accA[4][4], accB[4][4];

    // ---- pipeline stage lambdas (all fully inlined) ----
    auto prefetch_v = [&](int t1, float (&vreg)[16]) {
        if (t1 < NT) {
            const float* vsrc = kvb + (size_t)t1 * TM * CC + EE;
            #pragma unroll
            for (int i = 0; i < 4; i++) {
                int q = i * NTH + tid;             // 0..2047
                int r = q >> 5, c4 = q & 31;
                const float* s = vsrc + (size_t)r * CC + c4 * 4;
                vreg[i * 4 + 0] = s[0]; vreg[i * 4 + 1] = s[1];
                vreg[i * 4 + 2] = s[2]; vreg[i * 4 + 3] = s[3];
            }
        }
    };
    auto store_v = [&](int t1, float (&vreg)[16]) {
        if (t1 < NT) {
            char* dst = smem + OFF_V + (t1 & 3) * VBUF;
            #pragma unroll
            for (int i = 0; i < 4; i++) {
                int q = i * NTH + tid;
                int r = q >> 5, c4 = q & 31;
                uint32_t h01, l01, h23, l23;
                split2(vreg[i*4+0], vreg[i*4+1], h01, l01);
                split2(vreg[i*4+2], vreg[i*4+3], h23, l23);
                uint32_t off = (uint32_t)r * ROWB + (uint32_t)c4 * 8;
                *(uint2*)(dst + off)        = make_uint2(h01, h23);
                *(uint2*)(dst + VMAT + off) = make_uint2(l01, l23);
            }
        }
    };
    auto mma_tile = [&](int t, float (&acc)[4][4]) {
        const uint32_t vb    = sb + OFF_V + (uint32_t)(t & 3) * VBUF;
        const uint32_t b_hi0 = vb + b_row * ROWB + b_coff;
        const uint32_t b_lo0 = b_hi0 + VMAT;
        #pragma unroll
        for (int i = 0; i < 4; i++)
            #pragma unroll
            for (int j = 0; j < 4; j++) acc[i][j] = 0.f;
        #pragma unroll
        for (int k = 0; k < 8; k++) {              // e chunks of 16
            uint32_t ahi[4], alo[4];
            ldsm4(ahi, a_hi_base + (uint32_t)k * 32);
            ldsm4(alo, a_lo_base + (uint32_t)k * 32);
            uint32_t bhi[2][4], blo[2][4];
            #pragma unroll
            for (int p = 0; p < 2; p++) {          // this warp's two 16-col groups
                uint32_t boff = (uint32_t)(wm * 2 + p) * 16 * ROWB + (uint32_t)k * 32;
                ldsm4(bhi[p], b_hi0 + boff);
                ldsm4(blo[p], b_lo0 + boff);
            }
            #pragma unroll
            for (int p = 0; p < 2; p++) {          // hi*hi
                mma_bf16(acc[2*p],     ahi, bhi[p][0], bhi[p][1]);
                mma_bf16(acc[2*p + 1], ahi, bhi[p][2], bhi[p][3]);
            }
            #pragma unroll
            for (int p = 0; p < 2; p++) {          // hi*lo
                mma_bf16(acc[2*p],     ahi, blo[p][0], blo[p][1]);
                mma_bf16(acc[2*p + 1], ahi, blo[p][2], blo[p][3]);
            }
            #pragma unroll
            for (int p = 0; p < 2; p++) {          // lo*hi
                mma_bf16(acc[2*p],     alo, bhi[p][0], bhi[p][1]);
                mma_bf16(acc[2*p + 1], alo, bhi[p][2], bhi[p][3]);
            }
        }
    };
    auto epi = [&](int t, float (&acc)[4][4]) {
        const int mbase = t * TM + wm * 32;
        #pragma unroll
        for (int bi = 0; bi < 4; bi++) {
            #pragma unroll
            for (int cc = 0; cc < 2; cc++) {
                int ml = bi * 8 + (lane & 3) * 2 + cc;
                const float* pm = pos_s + (mbase + ml) * 3;
                float pmx = pm[0], pmy = pm[1], pmz = pm[2];
                {
                    float dx = pn0x - pmx, dy = pn0y - pmy, dz = pn0z - pmz;
                    float sq = fmaf(dx, dx, fmaf(dy, dy, fmaf(dz, dz, 1e-30f)));
                    float wg = acc[bi][cc] * rsqrtf(sq);     // diagonal: 0*finite=0
                    a0x = fmaf(dx, wg, a0x); a0y = fmaf(dy, wg, a0y); a0z = fmaf(dz, wg, a0z);
                }
                {
                    float dx = pn1x - pmx, dy = pn1y - pmy, dz = pn1z - pmz;
                    float sq = fmaf(dx, dx, fmaf(dy, dy, fmaf(dz, dz, 1e-30f)));
                    float wg = acc[bi][2 + cc] * rsqrtf(sq);
                    a1x = fmaf(dx, wg, a1x); a1y = fmaf(dy, wg, a1y); a1z = fmaf(dz, wg, a1z);
                }
            }
        }
    };

    // ---- pipelined loop, barrier every 2 tiles (quad-buffered V) ----
    {   // t = 0
        float vreg[16];
        prefetch_v(2, vreg);
        mma_tile(0, accA);
        store_v(2, vreg);
    }
    {   // t = 1
        float vreg[16];
        prefetch_v(3, vreg);
        mma_tile(1, accB);
        store_v(3, vreg);
        epi(0, accA);
        __syncthreads();
    }
    #pragma unroll 1
    for (int t = 2; t <= NT - 4; t += 2) {
        {   // even tile: MMA -> accA, epilogue(t-1) on accB
            float vreg[16];
            prefetch_v(t + 2, vreg);
            mma_tile(t, accA);
            store_v(t + 2, vreg);
            epi(t - 1, accB);
        }
        {   // odd tile: MMA -> accB, epilogue(t) on accA
            float vreg[16];
            prefetch_v(t + 3, vreg);
            mma_tile(t + 1, accB);
            store_v(t + 3, vreg);
            epi(t, accA);
            __syncthreads();
        }
    }
    {   // t = NT-2: nothing left to stage
        mma_tile(NT - 2, accA);
        epi(NT - 3, accB);
    }
    {   // t = NT-1
        mma_tile(NT - 1, accB);
        epi(NT - 2, accA);
        __syncthreads();
    }
    epi(NT - 1, accB);   // drain

    // ---- reduce across the 4 lanes of each quad (same rows, different m-cols) ----
    #pragma unroll
    for (int off = 1; off <= 2; off <<= 1) {
        a0x += __shfl_xor_sync(0xffffffffu, a0x, off);
        a0y += __shfl_xor_sync(0xffffffffu, a0y, off);
        a0z += __shfl_xor_sync(0xffffffffu, a0z, off);
        a1x += __shfl_xor_sync(0xffffffffu, a1x, off);
        a1y += __shfl_xor_sync(0xffffffffu, a1y, off);
        a1z += __shfl_xor_sync(0xffffffffu, a1z, off);
    }

    __syncthreads();   // all V reads done before scratch reuse
    // ---- combine the two m-col halves (warps w and w+8) via smem scratch ----
    float* scratch = (float*)(smem + OFF_V);      // V buffers dead now
    if (wm == 1 && (lane & 3) == 0) {
        scratch[r0loc * 3 + 0] = a0x;
        scratch[r0loc * 3 + 1] = a0y;
        scratch[r0loc * 3 + 2] = a0z;
        scratch[(r0loc + 8) * 3 + 0] = a1x;
        scratch[(r0loc + 8) * 3 + 1] = a1y;
        scratch[(r0loc + 8) * 3 + 2] = a1z;
    }
    __syncthreads();
    if (wm == 0 && (lane & 3) == 0) {
        float ax0 = a0x + scratch[r0loc * 3 + 0];
        float ay0 = a0y + scratch[r0loc * 3 + 1];
        float az0 = a0z + scratch[r0loc * 3 + 2];
        float ax1 = a1x + scratch[(r0loc + 8) * 3 + 0];
        float ay1 = a1y + scratch[(r0loc + 8) * 3 + 1];
        float az1 = a1z + scratch[(r0loc + 8) * 3 + 2];
        float* o0 = out + ((size_t)b * NN + n0 + r0loc) * 3;
        o0[0] = 0.01f * tanhf(ax0);
        o0[1] = 0.01f * tanhf(ay0);
        o0[2] = 0.01f * tanhf(az0);
        float* o1 = out + ((size_t)b * NN + n0 + r0loc + 8) * 3;
        o1[0] = 0.01f * tanhf(ax1);
        o1[1] = 0.01f * tanhf(ay1);
        o1[2] = 0.01f * tanhf(az1);
    }
}

extern "C" void kernel_launch(void* const* d_in, const int* in_sizes, int n_in,
                              void* d_out, int out_size)
{
    const float* kv  = (const float*)d_in[0];
    const float* pos = (const float*)d_in[1];
    float* out = (float*)d_out;
    (void)in_sizes; (void)n_in; (void)out_size;

    cudaFuncSetAttribute(actor_mma_kernel,
                         cudaFuncAttributeMaxDynamicSharedMemorySize, SMEM_TOTAL);

    dim3 grid(NN / TN, BATCH);   // (8,16) = 128 blocks
    actor_mma_kernel<<<grid, NTH, SMEM_TOTAL>>>(kv, pos, out);
}

// round 16
// speedup vs baseline: 1.6727x; 1.2505x over previous
#include <cuda_runtime.h>
#include <cuda_fp16.h>
#include <cstdint>
#include <math.h>

// kv (16,1024,259) f32, positions (16,1024,3) f32, out (16,1024,3) f32
#define BATCH     16
#define NN        1024
#define EE        128
#define CC        259
#define TN        128          // n rows per block
#define TM        64           // m cols per tile
#define NT        (NN / TM)    // 16 tiles
#define NTH       512          // 16 warps: 8 n-groups x 2 m-col halves
#define INV_SQRT_E 0.0883883476483184406f

// smem rows: 128 fp16 + 8 pad = 272 B (17 x 16B -> ldmatrix conflict-free)
#define ROWB      272
#define OFF_POS   0
#define POS_BYTES (NN * 3 * 4)               // 12288
#define OFF_KHI   (OFF_POS + POS_BYTES)      // 12288
#define KMAT      (TN * ROWB)                // 34816
#define OFF_KLO   (OFF_KHI + KMAT)           // 47104
#define OFF_V     (OFF_KLO + KMAT)           // 81920
#define VMAT      (TM * ROWB)                // 17408 (vhi only now)
#define SMEM_TOTAL (OFF_V + 4 * VMAT)        // 151552 B (quad-buffered vhi)

// ---------------- PTX helpers ----------------
__device__ __forceinline__ uint32_t smem_u32(const void* p) {
    uint32_t a;
    asm("{ .reg .u64 t; cvta.to.shared.u64 t, %1; cvt.u32.u64 %0, t; }" : "=r"(a) : "l"(p));
    return a;
}
__device__ __forceinline__ void ldsm4(uint32_t* r, uint32_t addr) {
    asm volatile("ldmatrix.sync.aligned.m8n8.x4.shared.b16 {%0,%1,%2,%3}, [%4];"
                 : "=r"(r[0]), "=r"(r[1]), "=r"(r[2]), "=r"(r[3]) : "r"(addr));
}
__device__ __forceinline__ void mma_f16(float* d, const uint32_t* a, uint32_t b0, uint32_t b1) {
    asm volatile(
        "mma.sync.aligned.m16n8k16.row.col.f32.f16.f16.f32 "
        "{%0,%1,%2,%3}, {%4,%5,%6,%7}, {%8,%9}, {%0,%1,%2,%3};"
        : "+f"(d[0]), "+f"(d[1]), "+f"(d[2]), "+f"(d[3])
        : "r"(a[0]), "r"(a[1]), "r"(a[2]), "r"(a[3]), "r"(b0), "r"(b1));
}
// split x into fp16 hi + fp16 lo (lo = fp16(x - float(hi))); pack pairs
__device__ __forceinline__ void split2h(float x0, float x1, uint32_t& hi, uint32_t& lo) {
    __half h0 = __float2half_rn(x0), h1 = __float2half_rn(x1);
    __half l0 = __float2half_rn(x0 - __half2float(h0));
    __half l1 = __float2half_rn(x1 - __half2float(h1));
    hi = (uint32_t)__half_as_ushort(h0) | ((uint32_t)__half_as_ushort(h1) << 16);
    lo = (uint32_t)__half_as_ushort(l0) | ((uint32_t)__half_as_ushort(l1) << 16);
}
__device__ __forceinline__ uint32_t pack2h(float x0, float x1) {
    __half h0 = __float2half_rn(x0), h1 = __float2half_rn(x1);
    return (uint32_t)__half_as_ushort(h0) | ((uint32_t)__half_as_ushort(h1) << 16);
}

__global__ __launch_bounds__(NTH, 1)
void actor_mma_kernel(const float* __restrict__ kv,
                      const float* __restrict__ pos,
                      float* __restrict__ out)
{
    extern __shared__ char smem[];
    const uint32_t sb = smem_u32(smem);
    float* pos_s = (float*)(smem + OFF_POS);

    const int tid  = threadIdx.x;
    const int w    = tid >> 5;
    const int lane = tid & 31;
    const int wn   = w & 7;            // n-row group: rows wn*16 .. wn*16+15
    const int wm   = w >> 3;           // m-col half: cols wm*32 .. wm*32+31 of each tile
    const int b    = blockIdx.y;
    const int n0   = blockIdx.x * TN;

    const float* kvb  = kv  + (size_t)b * NN * CC;
    const float* posb = pos + (size_t)b * NN * 3;

    // ---- stage all m positions ----
    for (int i = tid; i < NN * 3; i += NTH) pos_s[i] = posb[i];

    // ---- stage K (UNscaled; 1/sqrt(E) applied in epilogue), fp16 split hi/lo ----
    for (int q = tid; q < TN * 32; q += NTH) {           // 32 float4-groups/row
        int r = q >> 5, c4 = q & 31;
        const float* src = kvb + (size_t)(n0 + r) * CC + c4 * 4;
        uint32_t h01, l01, h23, l23;
        split2h(src[0], src[1], h01, l01);
        split2h(src[2], src[3], h23, l23);
        uint32_t off = (uint32_t)r * ROWB + (uint32_t)c4 * 8;
        *(uint2*)(smem + OFF_KHI + off) = make_uint2(h01, h23);
        *(uint2*)(smem + OFF_KLO + off) = make_uint2(l01, l23);
    }

    // ---- stage V tiles 0 and 1 (vhi only) ----
    for (int t0 = 0; t0 < 2; t0++) {
        char* dst = smem + OFF_V + t0 * VMAT;
        const float* vsrc = kvb + (size_t)t0 * TM * CC + EE;
        for (int q = tid; q < TM * 32; q += NTH) {
            int r = q >> 5, c4 = q & 31;
            const float* src = vsrc + (size_t)r * CC + c4 * 4;
            uint32_t off = (uint32_t)r * ROWB + (uint32_t)c4 * 8;
            *(uint2*)(dst + off) = make_uint2(pack2h(src[0], src[1]), pack2h(src[2], src[3]));
        }
    }
    __syncthreads();

    // ---- per-thread n-row state (2 rows) ----
    const int r0loc = wn * 16 + (lane >> 2);      // local n row; second = +8
    const float pn0x = posb[(size_t)(n0 + r0loc) * 3 + 0];
    const float pn0y = posb[(size_t)(n0 + r0loc) * 3 + 1];
    const float pn0z = posb[(size_t)(n0 + r0loc) * 3 + 2];
    const float pn1x = posb[(size_t)(n0 + r0loc + 8) * 3 + 0];
    const float pn1y = posb[(size_t)(n0 + r0loc + 8) * 3 + 1];
    const float pn1z = posb[(size_t)(n0 + r0loc + 8) * 3 + 2];
    float a0x = 0.f, a0y = 0.f, a0z = 0.f, a1x = 0.f, a1y = 0.f, a1z = 0.f;

    // ldmatrix lane address components
    const uint32_t a_row  = (uint32_t)(wn * 16 + (lane & 15));
    const uint32_t a_coff = (uint32_t)(lane >> 4) * 16;
    const uint32_t b_row  = (uint32_t)((lane & 7) + ((lane >> 4) & 1) * 8);
    const uint32_t b_coff = (uint32_t)((lane >> 3) & 1) * 16;
    const uint32_t a_hi_base = sb + OFF_KHI + a_row * ROWB + a_coff;
    const uint32_t a_lo_base = sb + OFF_KLO + a_row * ROWB + a_coff;

    float accA[4][4], accB[4][4];

    // ---- pipeline stage lambdas ----
    auto prefetch_v = [&](int t1, float (&vreg)[16]) {
        if (t1 < NT) {
            const float* vsrc = kvb + (size_t)t1 * TM * CC + EE;
            #pragma unroll
            for (int i = 0; i < 4; i++) {
                int q = i * NTH + tid;
                int r = q >> 5, c4 = q & 31;
                const float* s = vsrc + (size_t)r * CC + c4 * 4;
                vreg[i * 4 + 0] = s[0]; vreg[i * 4 + 1] = s[1];
                vreg[i * 4 + 2] = s[2]; vreg[i * 4 + 3] = s[3];
            }
        }
    };
    auto store_v = [&](int t1, float (&vreg)[16]) {
        if (t1 < NT) {
            char* dst = smem + OFF_V + (t1 & 3) * VMAT;
            #pragma unroll
            for (int i = 0; i < 4; i++) {
                int q = i * NTH + tid;
                int r = q >> 5, c4 = q & 31;
                uint32_t off = (uint32_t)r * ROWB + (uint32_t)c4 * 8;
                *(uint2*)(dst + off) = make_uint2(pack2h(vreg[i*4+0], vreg[i*4+1]),
                                                  pack2h(vreg[i*4+2], vreg[i*4+3]));
            }
        }
    };
    auto mma_tile = [&](int t, float (&acc)[4][4]) {
        const uint32_t vb    = sb + OFF_V + (uint32_t)(t & 3) * VMAT;
        const uint32_t b_hi0 = vb + b_row * ROWB + b_coff;
        #pragma unroll
        for (int i = 0; i < 4; i++)
            #pragma unroll
            for (int j = 0; j < 4; j++) acc[i][j] = 0.f;
        #pragma unroll
        for (int k = 0; k < 8; k++) {              // e chunks of 16
            uint32_t ahi[4], alo[4];
            ldsm4(ahi, a_hi_base + (uint32_t)k * 32);
            ldsm4(alo, a_lo_base + (uint32_t)k * 32);
            uint32_t bv[2][4];
            #pragma unroll
            for (int p = 0; p < 2; p++) {          // this warp's two 16-col groups
                uint32_t boff = (uint32_t)(wm * 2 + p) * 16 * ROWB + (uint32_t)k * 32;
                ldsm4(bv[p], b_hi0 + boff);
            }
            #pragma unroll
            for (int p = 0; p < 2; p++) {          // khi * v
                mma_f16(acc[2*p],     ahi, bv[p][0], bv[p][1]);
                mma_f16(acc[2*p + 1], ahi, bv[p][2], bv[p][3]);
            }
            #pragma unroll
            for (int p = 0; p < 2; p++) {          // klo * v
                mma_f16(acc[2*p],     alo, bv[p][0], bv[p][1]);
                mma_f16(acc[2*p + 1], alo, bv[p][2], bv[p][3]);
            }
        }
    };
    auto epi = [&](int t, float (&acc)[4][4]) {
        const int mbase = t * TM + wm * 32;
        #pragma unroll
        for (int bi = 0; bi < 4; bi++) {
            #pragma unroll
            for (int cc = 0; cc < 2; cc++) {
                int ml = bi * 8 + (lane & 3) * 2 + cc;
                const float* pm = pos_s + (mbase + ml) * 3;
                float pmx = pm[0], pmy = pm[1], pmz = pm[2];
                {
                    float dx = pn0x - pmx, dy = pn0y - pmy, dz = pn0z - pmz;
                    float sq = fmaf(dx, dx, fmaf(dy, dy, fmaf(dz, dz, 1e-30f)));
                    float wg = (acc[bi][cc] * INV_SQRT_E) * rsqrtf(sq); // diag: 0*finite=0
                    a0x = fmaf(dx, wg, a0x); a0y = fmaf(dy, wg, a0y); a0z = fmaf(dz, wg, a0z);
                }
                {
                    float dx = pn1x - pmx, dy = pn1y - pmy, dz = pn1z - pmz;
                    float sq = fmaf(dx, dx, fmaf(dy, dy, fmaf(dz, dz, 1e-30f)));
                    float wg = (acc[bi][2 + cc] * INV_SQRT_E) * rsqrtf(sq);
                    a1x = fmaf(dx, wg, a1x); a1y = fmaf(dy, wg, a1y); a1z = fmaf(dz, wg, a1z);
                }
            }
        }
    };

    // ---- pipelined loop, barrier every 2 tiles (quad-buffered V) ----
    {   // t = 0
        float vreg[16];
        prefetch_v(2, vreg);
        mma_tile(0, accA);
        store_v(2, vreg);
    }
    {   // t = 1
        float vreg[16];
        prefetch_v(3, vreg);
        mma_tile(1, accB);
        store_v(3, vreg);
        epi(0, accA);
        __syncthreads();
    }
    #pragma unroll 1
    for (int t = 2; t <= NT - 4; t += 2) {
        {
            float vreg[16];
            prefetch_v(t + 2, vreg);
            mma_tile(t, accA);
            store_v(t + 2, vreg);
            epi(t - 1, accB);
        }
        {
            float vreg[16];
            prefetch_v(t + 3, vreg);
            mma_tile(t + 1, accB);
            store_v(t + 3, vreg);
            epi(t, accA);
            __syncthreads();
        }
    }
    {   // t = NT-2
        mma_tile(NT - 2, accA);
        epi(NT - 3, accB);
    }
    {   // t = NT-1
        mma_tile(NT - 1, accB);
        epi(NT - 2, accA);
        __syncthreads();
    }
    epi(NT - 1, accB);   // drain

    // ---- reduce across the 4 lanes of each quad ----
    #pragma unroll
    for (int off = 1; off <= 2; off <<= 1) {
        a0x += __shfl_xor_sync(0xffffffffu, a0x, off);
        a0y += __shfl_xor_sync(0xffffffffu, a0y, off);
        a0z += __shfl_xor_sync(0xffffffffu, a0z, off);
        a1x += __shfl_xor_sync(0xffffffffu, a1x, off);
        a1y += __shfl_xor_sync(0xffffffffu, a1y, off);
        a1z += __shfl_xor_sync(0xffffffffu, a1z, off);
    }

    __syncthreads();   // all V reads done before scratch reuse
    // ---- combine the two m-col halves (warps w and w+8) via smem scratch ----
    float* scratch = (float*)(smem + OFF_V);
    if (wm == 1 && (lane & 3) == 0) {
        scratch[r0loc * 3 + 0] = a0x;
        scratch[r0loc * 3 + 1] = a0y;
        scratch[r0loc * 3 + 2] = a0z;
        scratch[(r0loc + 8) * 3 + 0] = a1x;
        scratch[(r0loc + 8) * 3 + 1] = a1y;
        scratch[(r0loc + 8) * 3 + 2] = a1z;
    }
    __syncthreads();
    if (wm == 0 && (lane & 3) == 0) {
        float ax0 = a0x + scratch[r0loc * 3 + 0];
        float ay0 = a0y + scratch[r0loc * 3 + 1];
        float az0 = a0z + scratch[r0loc * 3 + 2];
        float ax1 = a1x + scratch[(r0loc + 8) * 3 + 0];
        float ay1 = a1y + scratch[(r0loc + 8) * 3 + 1];
        float az1 = a1z + scratch[(r0loc + 8) * 3 + 2];
        float* o0 = out + ((size_t)b * NN + n0 + r0loc) * 3;
        o0[0] = 0.01f * tanhf(ax0);
        o0[1] = 0.01f * tanhf(ay0);
        o0[2] = 0.01f * tanhf(az0);
        float* o1 = out + ((size_t)b * NN + n0 + r0loc + 8) * 3;
        o1[0] = 0.01f * tanhf(ax1);
        o1[1] = 0.01f * tanhf(ay1);
        o1[2] = 0.01f * tanhf(az1);
    }
}

extern "C" void kernel_launch(void* const* d_in, const int* in_sizes, int n_in,
                              void* d_out, int out_size)
{
    const float* kv  = (const float*)d_in[0];
    const float* pos = (const float*)d_in[1];
    float* out = (float*)d_out;
    (void)in_sizes; (void)n_in; (void)out_size;

    cudaFuncSetAttribute(actor_mma_kernel,
                         cudaFuncAttributeMaxDynamicSharedMemorySize, SMEM_TOTAL);

    dim3 grid(NN / TN, BATCH);   // (8,16) = 128 blocks
    actor_mma_kernel<<<grid, NTH, SMEM_TOTAL>>>(kv, pos, out);
}